// round 7
// baseline (speedup 1.0000x reference)
#include <cuda_runtime.h>
#include <cuda_bf16.h>
#include <math.h>
#include <stdint.h>

// ---------------- problem constants ----------------
#define Bz 32
#define TE 2048
#define TDd 64
#define Dd 1024
#define Mrows (Bz * TE)      // 65536

// ---------------- scratch (device globals) ----------------
__device__ char  g_A1[(size_t)Mrows * Dd];   // 64 MB high digit of enc
__device__ char  g_A2[(size_t)Mrows * Dd];   // 64 MB low digit
__device__ char  g_W1[(size_t)Dd * Dd];      // W^T high digit [n][k]
__device__ char  g_W2[(size_t)Dd * Dd];      // W^T low digit
__device__ float g_sA[Mrows];
__device__ float g_sB[Dd];
__device__ float g_dU[Bz * Dd];
__device__ float g_scores[Bz * TE];
__device__ float g_weights[Bz * TE];

// ---------------- helpers ----------------
__device__ __forceinline__ uint32_t smem_to_u32(const void* p) {
    uint32_t a;
    asm("{ .reg .u64 t; cvta.to.shared.u64 t, %1; cvt.u32.u64 %0, t; }" : "=r"(a) : "l"(p));
    return a;
}
__device__ __forceinline__ void cp16(uint32_t s, const void* g) {
    asm volatile("cp.async.cg.shared.global [%0], [%1], 16;" :: "r"(s), "l"(g));
}
#define CP_COMMIT() asm volatile("cp.async.commit_group;" ::: "memory")
#define CP_WAIT(n)  asm volatile("cp.async.wait_group %0;" :: "n"(n) : "memory")
#define LDSM_X4(r0, r1, r2, r3, addr) \
    asm volatile("ldmatrix.sync.aligned.m8n8.x4.shared.b16 {%0,%1,%2,%3}, [%4];" \
        : "=r"(r0), "=r"(r1), "=r"(r2), "=r"(r3) : "r"(addr))
#define IMMA16832(d0, d1, d2, d3, a0, a1, a2, a3, b0, b1) \
    asm volatile("mma.sync.aligned.m16n8k32.row.col.s32.s8.s8.s32 " \
        "{%0,%1,%2,%3}, {%4,%5,%6,%7}, {%8,%9}, {%0,%1,%2,%3};" \
        : "+r"(d0), "+r"(d1), "+r"(d2), "+r"(d3) \
        : "r"(a0), "r"(a1), "r"(a2), "r"(a3), "r"(b0), "r"(b1))

__device__ __forceinline__ uint32_t sw128(uint32_t off) {
    return off ^ ((off >> 3) & 0x70);
}
__device__ __forceinline__ void quant2(float x, float inv, int& q1, int& q2) {
    int T = __float2int_rn(x * inv);
    int a1 = (T + (T >= 0 ? 64 : -64)) / 128;
    if (a1 > 127) a1 = 127;
    if (a1 < -128) a1 = -128;
    q1 = a1;
    q2 = T - 128 * a1;
}

// ---------------- GEMM tiling ----------------
#define BM 128
#define BN 128
#define BKE 128                     // int8 k per chunk (128 B rows)
#define NKC 8                       // 1024 / 128
#define STG_B 65536                 // per-stage: A1 16K + A2 16K + B1 16K + B2 16K
#define SMEM_TOTAL (3 * STG_B)      // 192 KB, 3 stages

// ---------------- setup kernels ----------------
// one block (128 threads) per A row
__global__ void quant_A_kernel(const float* __restrict__ enc) {
    const int r = blockIdx.x;
    const int tid = threadIdx.x;
    const float* row = enc + (size_t)r * Dd;
    float4 v0 = *(const float4*)(row + tid * 8);
    float4 v1 = *(const float4*)(row + tid * 8 + 4);
    float vals[8] = {v0.x, v0.y, v0.z, v0.w, v1.x, v1.y, v1.z, v1.w};
    float mx = 0.0f;
#pragma unroll
    for (int i = 0; i < 8; i++) mx = fmaxf(mx, fabsf(vals[i]));
#pragma unroll
    for (int o = 16; o > 0; o >>= 1) mx = fmaxf(mx, __shfl_xor_sync(0xFFFFFFFF, mx, o));
    __shared__ float sm[4];
    if ((tid & 31) == 0) sm[tid >> 5] = mx;
    __syncthreads();
    mx = fmaxf(fmaxf(sm[0], sm[1]), fmaxf(sm[2], sm[3]));
    float s, inv;
    if (mx > 0.0f) { s = mx * (1.0f / 16383.0f); inv = 16383.0f / mx; }
    else           { s = 1.0f; inv = 0.0f; }
    if (tid == 0) g_sA[r] = s;
    char q1[8], q2[8];
#pragma unroll
    for (int i = 0; i < 8; i++) {
        int a1, a2;
        quant2(vals[i], inv, a1, a2);
        q1[i] = (char)a1; q2[i] = (char)a2;
    }
    *(uint2*)(g_A1 + (size_t)r * Dd + tid * 8) = *(uint2*)q1;
    *(uint2*)(g_A2 + (size_t)r * Dd + tid * 8) = *(uint2*)q2;
}

// one block (256 threads) per W^T row (output feature n)
__global__ void quant_W_kernel(const float* __restrict__ W) {
    const int n = blockIdx.x;
    const int tid = threadIdx.x;
    float w[4];
#pragma unroll
    for (int j = 0; j < 4; j++) w[j] = W[(size_t)(tid + j * 256) * Dd + n];
    float mx = 0.0f;
#pragma unroll
    for (int j = 0; j < 4; j++) mx = fmaxf(mx, fabsf(w[j]));
#pragma unroll
    for (int o = 16; o > 0; o >>= 1) mx = fmaxf(mx, __shfl_xor_sync(0xFFFFFFFF, mx, o));
    __shared__ float sm[8];
    if ((tid & 31) == 0) sm[tid >> 5] = mx;
    __syncthreads();
    if (tid < 8) {
        float m2 = sm[tid];
#pragma unroll
        for (int o = 4; o > 0; o >>= 1) m2 = fmaxf(m2, __shfl_xor_sync(0xFF, m2, o));
        if (tid == 0) sm[0] = m2;
    }
    __syncthreads();
    mx = sm[0];
    float s, inv;
    if (mx > 0.0f) { s = mx * (1.0f / 16383.0f); inv = 16383.0f / mx; }
    else           { s = 1.0f; inv = 0.0f; }
    if (tid == 0) g_sB[n] = s;
#pragma unroll
    for (int j = 0; j < 4; j++) {
        int a1, a2;
        quant2(w[j], inv, a1, a2);
        g_W1[(size_t)n * Dd + tid + j * 256] = (char)a1;
        g_W2[(size_t)n * Dd + tid + j * 256] = (char)a2;
    }
}

__global__ void zero_kernel() {
    int i = blockIdx.x * blockDim.x + threadIdx.x;
    if (i < Bz * TE) g_scores[i] = 0.0f;
    if (i < Bz * Dd) g_dU[i] = 0.0f;
}

// dU[b][f] = sum_k dec_last[b][k] * U[k][f]  ; grid (4, 32)
__global__ void dU_kernel(const float* __restrict__ dec, const float* __restrict__ U) {
    const int f  = blockIdx.x * 256 + threadIdx.x;
    const int k0 = blockIdx.y * 32;
    __shared__ float sdec[Bz][32];
#pragma unroll
    for (int j = 0; j < 4; j++) {
        int idx = threadIdx.x + j * 256;
        int b = idx >> 5, kk = idx & 31;
        sdec[b][kk] = dec[((size_t)b * TDd + (TDd - 1)) * Dd + k0 + kk];
    }
    __syncthreads();
    float acc[Bz];
#pragma unroll
    for (int b = 0; b < Bz; b++) acc[b] = 0.0f;
#pragma unroll
    for (int kk = 0; kk < 32; kk++) {
        float u = U[(size_t)(k0 + kk) * Dd + f];
#pragma unroll
        for (int b = 0; b < Bz; b++) acc[b] = fmaf(u, sdec[b][kk], acc[b]);
    }
#pragma unroll
    for (int b = 0; b < Bz; b++) atomicAdd(&g_dU[b * Dd + f], acc[b]);
}

// ---------------- fused int8 GEMM + epilogue ----------------
// stage layout: A1 at +0, A2 at +16K, B1 at +32K, B2 at +48K
__device__ __forceinline__ void load_chunk(uint32_t sbase, int stage, int c,
                                           int mbase, int nbase, int tid) {
    const int kb = c * BKE;
    uint32_t st = sbase + stage * STG_B;
#pragma unroll
    for (int i = 0; i < 2; i++) {
        int u = tid + i * 512;                  // 0..1023
        int r = u >> 3, ch = u & 7;
        uint32_t off = sw128((uint32_t)(r * 128 + ch * 16));
        size_t ga = (size_t)(mbase + r) * Dd + kb + ch * 16;
        size_t gb = (size_t)(nbase + r) * Dd + kb + ch * 16;
        cp16(st + off,         g_A1 + ga);
        cp16(st + 16384 + off, g_A2 + ga);
        cp16(st + 32768 + off, g_W1 + gb);
        cp16(st + 49152 + off, g_W2 + gb);
    }
    CP_COMMIT();
}

__global__ void __launch_bounds__(512, 1) gemm_score_i8(const float* __restrict__ V) {
    extern __shared__ char smem[];
    uint32_t sbase = smem_to_u32(smem);

    const int tid  = threadIdx.x;
    const int wid  = tid >> 5;
    const int lane = tid & 31;
    const int wm   = wid >> 3;      // 0..1 : 64 rows
    const int wn   = wid & 7;       // 0..7 : 16 cols

    const int nblk  = blockIdx.x & 7;
    const int mblk  = blockIdx.x >> 3;
    const int mbase = mblk * BM;
    const int nbase = nblk * BN;
    const int b     = mbase >> 11;

    int hi[4][2][4], md[4][2][4];
#pragma unroll
    for (int mt = 0; mt < 4; mt++)
#pragma unroll
        for (int nt = 0; nt < 2; nt++)
#pragma unroll
            for (int i = 0; i < 4; i++) { hi[mt][nt][i] = 0; md[mt][nt][i] = 0; }

    const int a_r  = lane & 15;
    const int a_kc = lane >> 4;
    const int b_n  = ((lane >> 4) & 1) * 8 + (lane & 7);
    const int b_kc = (lane >> 3) & 1;

    load_chunk(sbase, 0, 0, mbase, nbase, tid);
    load_chunk(sbase, 1, 1, mbase, nbase, tid);

    int stage = 0;
    for (int c = 0; c < NKC; c++) {
        if (c + 2 < NKC) { CP_WAIT(1); } else { CP_WAIT(0); }
        __syncthreads();
        if (c + 2 < NKC) {
            int ns = stage + 2; if (ns >= 3) ns -= 3;
            load_chunk(sbase, ns, c + 2, mbase, nbase, tid);
        }

        const uint32_t st  = sbase + stage * STG_B;
        const uint32_t sA1 = st;
        const uint32_t sA2 = st + 16384;
        const uint32_t sB1 = st + 32768;
        const uint32_t sB2 = st + 49152;

#pragma unroll
        for (int ks = 0; ks < 4; ks++) {
            uint32_t bf1[4], bf2[4], af[4][4];
            {
                int row = wn * 16 + b_n;
                uint32_t off = sw128((uint32_t)(row * 128 + (ks * 2 + b_kc) * 16));
                LDSM_X4(bf1[0], bf1[1], bf1[2], bf1[3], sB1 + off);
                LDSM_X4(bf2[0], bf2[1], bf2[2], bf2[3], sB2 + off);
            }
#pragma unroll
            for (int mt = 0; mt < 4; mt++) {
                int row = wm * 64 + mt * 16 + a_r;
                uint32_t off = sw128((uint32_t)(row * 128 + (ks * 2 + a_kc) * 16));
                LDSM_X4(af[mt][0], af[mt][1], af[mt][2], af[mt][3], sA1 + off);
            }
            // a1*b1 -> hi ; a1*b2 -> mid
#pragma unroll
            for (int mt = 0; mt < 4; mt++)
#pragma unroll
                for (int nt = 0; nt < 2; nt++) {
                    IMMA16832(hi[mt][nt][0], hi[mt][nt][1], hi[mt][nt][2], hi[mt][nt][3],
                              af[mt][0], af[mt][1], af[mt][2], af[mt][3],
                              bf1[nt * 2], bf1[nt * 2 + 1]);
                    IMMA16832(md[mt][nt][0], md[mt][nt][1], md[mt][nt][2], md[mt][nt][3],
                              af[mt][0], af[mt][1], af[mt][2], af[mt][3],
                              bf2[nt * 2], bf2[nt * 2 + 1]);
                }
            // a2*b1 -> mid
#pragma unroll
            for (int mt = 0; mt < 4; mt++) {
                int row = wm * 64 + mt * 16 + a_r;
                uint32_t off = sw128((uint32_t)(row * 128 + (ks * 2 + a_kc) * 16));
                LDSM_X4(af[mt][0], af[mt][1], af[mt][2], af[mt][3], sA2 + off);
            }
#pragma unroll
            for (int mt = 0; mt < 4; mt++)
#pragma unroll
                for (int nt = 0; nt < 2; nt++)
                    IMMA16832(md[mt][nt][0], md[mt][nt][1], md[mt][nt][2], md[mt][nt][3],
                              af[mt][0], af[mt][1], af[mt][2], af[mt][3],
                              bf1[nt * 2], bf1[nt * 2 + 1]);
        }
        stage++; if (stage >= 3) stage = 0;
    }

    // ---- fused epilogue ----
    const int q  = lane >> 2;
    const int t4 = lane & 3;
    float vv[2][2], uu[2][2], sb[2][2];
#pragma unroll
    for (int nt = 0; nt < 2; nt++) {
        int n0 = nbase + wn * 16 + nt * 8 + t4 * 2;
        vv[nt][0] = V[n0];           vv[nt][1] = V[n0 + 1];
        uu[nt][0] = g_dU[b * Dd + n0]; uu[nt][1] = g_dU[b * Dd + n0 + 1];
        sb[nt][0] = g_sB[n0];        sb[nt][1] = g_sB[n0 + 1];
    }
#pragma unroll
    for (int mt = 0; mt < 4; mt++) {
        int m0 = mbase + wm * 64 + mt * 16 + q;
        float sa0 = g_sA[m0], sa1 = g_sA[m0 + 8];
        float s0 = 0.0f, s1 = 0.0f;
#pragma unroll
        for (int nt = 0; nt < 2; nt++) {
#pragma unroll
            for (int j = 0; j < 2; j++) {
                float f0 = 16384.0f * (float)hi[mt][nt][j]     + 128.0f * (float)md[mt][nt][j];
                float f1 = 16384.0f * (float)hi[mt][nt][2 + j] + 128.0f * (float)md[mt][nt][2 + j];
                float c0 = sa0 * sb[nt][j] * f0;
                float c1 = sa1 * sb[nt][j] * f1;
                s0 = fmaf(vv[nt][j], tanhf(c0 + uu[nt][j]), s0);
                s1 = fmaf(vv[nt][j], tanhf(c1 + uu[nt][j]), s1);
            }
        }
        s0 += __shfl_xor_sync(0xFFFFFFFF, s0, 1);
        s0 += __shfl_xor_sync(0xFFFFFFFF, s0, 2);
        s1 += __shfl_xor_sync(0xFFFFFFFF, s1, 1);
        s1 += __shfl_xor_sync(0xFFFFFFFF, s1, 2);
        if (t4 == 0) {
            atomicAdd(&g_scores[m0], s0);
            atomicAdd(&g_scores[m0 + 8], s1);
        }
    }
}

// ---------------- softmax & context ----------------
__global__ void softmax_kernel(float* __restrict__ out_weights) {
    const int b = blockIdx.x;
    const int tid = threadIdx.x;
    __shared__ float red[256];
    float local[8];
    float mx = -INFINITY;
#pragma unroll
    for (int i = 0; i < 8; i++) {
        local[i] = g_scores[b * TE + tid + i * 256];
        mx = fmaxf(mx, local[i]);
    }
    red[tid] = mx;
    __syncthreads();
    for (int s = 128; s > 0; s >>= 1) {
        if (tid < s) red[tid] = fmaxf(red[tid], red[tid + s]);
        __syncthreads();
    }
    mx = red[0];
    __syncthreads();
    float sum = 0.0f;
#pragma unroll
    for (int i = 0; i < 8; i++) { local[i] = expf(local[i] - mx); sum += local[i]; }
    red[tid] = sum;
    __syncthreads();
    for (int s = 128; s > 0; s >>= 1) {
        if (tid < s) red[tid] += red[tid + s];
        __syncthreads();
    }
    const float inv = 1.0f / red[0];
#pragma unroll
    for (int i = 0; i < 8; i++) {
        float w = local[i] * inv;
        g_weights[b * TE + tid + i * 256]   = w;
        out_weights[b * TE + tid + i * 256] = w;
    }
}

__global__ void context_kernel(const float* __restrict__ enc, float* __restrict__ out_context) {
    const int b = blockIdx.x;
    const int e = blockIdx.y * 256 + threadIdx.x;
    __shared__ float sw[TE];
    for (int i = threadIdx.x; i < TE; i += 256) sw[i] = g_weights[b * TE + i];
    __syncthreads();
    const float* base = enc + (size_t)b * TE * Dd + e;
    float acc = 0.0f;
#pragma unroll 8
    for (int t = 0; t < TE; t++) acc = fmaf(sw[t], base[(size_t)t * Dd], acc);
    out_context[b * Dd + e] = acc;
}

// ---------------- launch ----------------
extern "C" void kernel_launch(void* const* d_in, const int* in_sizes, int n_in,
                              void* d_out, int out_size) {
    const float* enc = (const float*)d_in[0];
    const float* dec = (const float*)d_in[1];
    const float* W_a = (const float*)d_in[2];
    const float* U_a = (const float*)d_in[3];
    const float* V_a = (const float*)d_in[4];
    float* out = (float*)d_out;
    float* out_context = out;            // 32*1024
    float* out_weights = out + Bz * Dd;  // 32*2048

    static int smem_set = 0;
    if (!smem_set) {
        cudaFuncSetAttribute(gemm_score_i8, cudaFuncAttributeMaxDynamicSharedMemorySize, SMEM_TOTAL);
        smem_set = 1;
    }

    quant_A_kernel<<<Mrows, 128>>>(enc);
    quant_W_kernel<<<Dd, 256>>>(W_a);
    zero_kernel<<<(Bz * TE + 255) / 256, 256>>>();
    {
        dim3 g(Dd / 256, 32);
        dU_kernel<<<g, 256>>>(dec, U_a);
    }
    gemm_score_i8<<<(Mrows / BM) * (Dd / BN), 512, SMEM_TOTAL>>>(V_a);
    softmax_kernel<<<Bz, 256>>>(out_weights);
    {
        dim3 g(Bz, Dd / 256);
        context_kernel<<<g, 256>>>(enc, out_context);
    }
}

// round 8
// speedup vs baseline: 3.5070x; 3.5070x over previous
#include <cuda_runtime.h>
#include <cuda_fp16.h>
#include <math.h>
#include <stdint.h>

// ---------------- problem constants ----------------
#define Bz 32
#define TE 2048
#define TDd 64
#define Dd 1024
#define Mrows (Bz * TE)      // 65536

// ---------------- scratch (device globals) ----------------
__device__ __half g_A1[(size_t)Mrows * Dd];   // fp16(enc)
__device__ __half g_A2[(size_t)Mrows * Dd];   // fp16 residual
__device__ __half g_B1[(size_t)Dd * Dd];      // W^T fp16 : [n][k]
__device__ float g_dU[Bz * Dd];
__device__ float g_scores[Bz * TE];
__device__ float g_weights[Bz * TE];

// ---------------- helpers ----------------
__device__ __forceinline__ uint32_t smem_to_u32(const void* p) {
    uint32_t a;
    asm("{ .reg .u64 t; cvta.to.shared.u64 t, %1; cvt.u32.u64 %0, t; }" : "=r"(a) : "l"(p));
    return a;
}
__device__ __forceinline__ void cp16(uint32_t s, const void* g) {
    asm volatile("cp.async.cg.shared.global [%0], [%1], 16;" :: "r"(s), "l"(g));
}
#define CP_COMMIT() asm volatile("cp.async.commit_group;" ::: "memory")
#define CP_WAIT(n)  asm volatile("cp.async.wait_group %0;" :: "n"(n) : "memory")
#define LDSM_X4(r0, r1, r2, r3, addr) \
    asm volatile("ldmatrix.sync.aligned.m8n8.x4.shared.b16 {%0,%1,%2,%3}, [%4];" \
        : "=r"(r0), "=r"(r1), "=r"(r2), "=r"(r3) : "r"(addr))
#define MMA16816F(d0, d1, d2, d3, a0, a1, a2, a3, b0, b1) \
    asm volatile("mma.sync.aligned.m16n8k16.row.col.f32.f16.f16.f32 " \
        "{%0,%1,%2,%3}, {%4,%5,%6,%7}, {%8,%9}, {%0,%1,%2,%3};" \
        : "+f"(d0), "+f"(d1), "+f"(d2), "+f"(d3) \
        : "r"(a0), "r"(a1), "r"(a2), "r"(a3), "r"(b0), "r"(b1))

__device__ __forceinline__ uint32_t sw128(uint32_t off) {
    return off ^ ((off >> 3) & 0x70);
}

// ---------------- GEMM tiling ----------------
#define BM 128
#define BN 128
#define BKE 64                      // fp16 k per chunk (128 B rows)
#define NKC2 32                     // 2 split phases * 16 k-chunks
#define STG_B 32768                 // per-stage bytes: A 16K + B 16K
#define SMEM_TOTAL (3 * STG_B)      // 96 KB

// ---------------- setup kernels ----------------
// 8 floats per thread
__global__ void convert_A_kernel(const float* __restrict__ enc) {
    size_t i = ((size_t)blockIdx.x * blockDim.x + threadIdx.x) * 8;
    float4 v0 = *(const float4*)(enc + i);
    float4 v1 = *(const float4*)(enc + i + 4);
    __half2 h[4];
    h[0] = __floats2half2_rn(v0.x, v0.y);
    h[1] = __floats2half2_rn(v0.z, v0.w);
    h[2] = __floats2half2_rn(v1.x, v1.y);
    h[3] = __floats2half2_rn(v1.z, v1.w);
    *(uint4*)(g_A1 + i) = *(uint4*)h;
    __half2 l[4];
    l[0] = __floats2half2_rn(v0.x - __half2float(h[0].x), v0.y - __half2float(h[0].y));
    l[1] = __floats2half2_rn(v0.z - __half2float(h[1].x), v0.w - __half2float(h[1].y));
    l[2] = __floats2half2_rn(v1.x - __half2float(h[2].x), v1.y - __half2float(h[2].y));
    l[3] = __floats2half2_rn(v1.z - __half2float(h[3].x), v1.w - __half2float(h[3].y));
    *(uint4*)(g_A2 + i) = *(uint4*)l;
}

__global__ void convert_W_kernel(const float* __restrict__ W) {
    int id = blockIdx.x * 256 + threadIdx.x;
    int n = id >> 10, k = id & 1023;
    g_B1[(size_t)n * Dd + k] = __float2half(W[(size_t)k * Dd + n]);  // transpose
}

__global__ void zero_kernel() {
    int i = blockIdx.x * blockDim.x + threadIdx.x;
    if (i < Bz * TE) g_scores[i] = 0.0f;
    if (i < Bz * Dd) g_dU[i] = 0.0f;
}

// dU[b][f] = sum_k dec_last[b][k] * U[k][f]  ; grid (4, 32)
__global__ void dU_kernel(const float* __restrict__ dec, const float* __restrict__ U) {
    const int f  = blockIdx.x * 256 + threadIdx.x;
    const int k0 = blockIdx.y * 32;
    __shared__ float sdec[Bz][32];
#pragma unroll
    for (int j = 0; j < 4; j++) {
        int idx = threadIdx.x + j * 256;
        int b = idx >> 5, kk = idx & 31;
        sdec[b][kk] = dec[((size_t)b * TDd + (TDd - 1)) * Dd + k0 + kk];
    }
    __syncthreads();
    float acc[Bz];
#pragma unroll
    for (int b = 0; b < Bz; b++) acc[b] = 0.0f;
#pragma unroll
    for (int kk = 0; kk < 32; kk++) {
        float u = U[(size_t)(k0 + kk) * Dd + f];
#pragma unroll
        for (int b = 0; b < Bz; b++) acc[b] = fmaf(u, sdec[b][kk], acc[b]);
    }
#pragma unroll
    for (int b = 0; b < Bz; b++) atomicAdd(&g_dU[b * Dd + f], acc[b]);
}

// ---------------- fused GEMM + epilogue ----------------
__device__ __forceinline__ void load_chunk(uint32_t sbase, int stage, int c,
                                           int mbase, int nbase, int tid) {
    const int phase = c >> 4;           // 0: A1, 1: A2
    const int kb = (c & 15) * BKE;
    const __half* Ap = phase ? g_A2 : g_A1;
    uint32_t sA = sbase + stage * STG_B;
    uint32_t sB = sA + 16384;
#pragma unroll
    for (int i = 0; i < 4; i++) {
        int u = tid + i * 256;                 // 0..1023
        int r = u >> 3, ch = u & 7;
        uint32_t off = sw128((uint32_t)(r * 128 + ch * 16));
        cp16(sA + off, Ap + (size_t)(mbase + r) * Dd + kb + ch * 8);
        cp16(sB + off, g_B1 + (size_t)(nbase + r) * Dd + kb + ch * 8);
    }
    CP_COMMIT();
}

__global__ void __launch_bounds__(256, 2) gemm_score_mma(const float* __restrict__ V) {
    extern __shared__ char smem[];
    uint32_t sbase = smem_to_u32(smem);

    const int tid  = threadIdx.x;
    const int wid  = tid >> 5;
    const int lane = tid & 31;
    const int wm   = wid >> 2;      // 0..1
    const int wn   = wid & 3;       // 0..3

    const int nblk  = blockIdx.x & 7;
    const int mblk  = blockIdx.x >> 3;
    const int mbase = mblk * BM;
    const int nbase = nblk * BN;
    const int b     = mbase >> 11;

    float acc[4][4][4];
#pragma unroll
    for (int mt = 0; mt < 4; mt++)
#pragma unroll
        for (int nt = 0; nt < 4; nt++)
#pragma unroll
            for (int i = 0; i < 4; i++) acc[mt][nt][i] = 0.0f;

    const int a_r  = lane & 15;
    const int a_kc = lane >> 4;
    const int b_n  = ((lane >> 4) & 1) * 8 + (lane & 7);
    const int b_kc = (lane >> 3) & 1;

    // prologue: stages 0,1
    load_chunk(sbase, 0, 0, mbase, nbase, tid);
    load_chunk(sbase, 1, 1, mbase, nbase, tid);

    int stage = 0;
    for (int c = 0; c < NKC2; c++) {
        if (c + 2 < NKC2) { CP_WAIT(1); } else { CP_WAIT(0); }
        __syncthreads();
        if (c + 2 < NKC2) {
            int ns = stage + 2; if (ns >= 3) ns -= 3;
            load_chunk(sbase, ns, c + 2, mbase, nbase, tid);
        }

        const uint32_t sA = sbase + stage * STG_B;
        const uint32_t sB = sA + 16384;
#pragma unroll
        for (int ks = 0; ks < 4; ks++) {
            uint32_t af[4][4], bf[2][4];
#pragma unroll
            for (int mt = 0; mt < 4; mt++) {
                int row = wm * 64 + mt * 16 + a_r;
                uint32_t off = sw128((uint32_t)(row * 128 + (ks * 2 + a_kc) * 16));
                LDSM_X4(af[mt][0], af[mt][1], af[mt][2], af[mt][3], sA + off);
            }
#pragma unroll
            for (int p = 0; p < 2; p++) {
                int row = wn * 32 + p * 16 + b_n;
                uint32_t off = sw128((uint32_t)(row * 128 + (ks * 2 + b_kc) * 16));
                LDSM_X4(bf[p][0], bf[p][1], bf[p][2], bf[p][3], sB + off);
            }
#pragma unroll
            for (int mt = 0; mt < 4; mt++)
#pragma unroll
                for (int nt = 0; nt < 4; nt++)
                    MMA16816F(acc[mt][nt][0], acc[mt][nt][1], acc[mt][nt][2], acc[mt][nt][3],
                              af[mt][0], af[mt][1], af[mt][2], af[mt][3],
                              bf[nt >> 1][(nt & 1) * 2], bf[nt >> 1][(nt & 1) * 2 + 1]);
        }
        stage++; if (stage >= 3) stage = 0;
    }

    // ---- fused epilogue: scores[m] += sum_n V[n]*tanh(C[m][n] + dU[b][n]) ----
    const int q = lane >> 2;
    const int t4 = lane & 3;
#pragma unroll
    for (int mt = 0; mt < 4; mt++) {
        float s0 = 0.0f, s1 = 0.0f;
#pragma unroll
        for (int nt = 0; nt < 4; nt++) {
            int n0 = nbase + wn * 32 + nt * 8 + 2 * t4;
            float v0 = V[n0], v1 = V[n0 + 1];
            float u0 = g_dU[b * Dd + n0], u1 = g_dU[b * Dd + n0 + 1];
            s0 = fmaf(v0, tanhf(acc[mt][nt][0] + u0), s0);
            s0 = fmaf(v1, tanhf(acc[mt][nt][1] + u1), s0);
            s1 = fmaf(v0, tanhf(acc[mt][nt][2] + u0), s1);
            s1 = fmaf(v1, tanhf(acc[mt][nt][3] + u1), s1);
        }
        s0 += __shfl_xor_sync(0xFFFFFFFF, s0, 1);
        s0 += __shfl_xor_sync(0xFFFFFFFF, s0, 2);
        s1 += __shfl_xor_sync(0xFFFFFFFF, s1, 1);
        s1 += __shfl_xor_sync(0xFFFFFFFF, s1, 2);
        if (t4 == 0) {
            int row = mbase + wm * 64 + mt * 16 + q;
            atomicAdd(&g_scores[row], s0);
            atomicAdd(&g_scores[row + 8], s1);
        }
    }
}

// ---------------- softmax & context ----------------
__global__ void softmax_kernel(float* __restrict__ out_weights) {
    const int b = blockIdx.x;
    const int tid = threadIdx.x;
    __shared__ float red[256];
    float local[8];
    float mx = -INFINITY;
#pragma unroll
    for (int i = 0; i < 8; i++) {
        local[i] = g_scores[b * TE + tid + i * 256];
        mx = fmaxf(mx, local[i]);
    }
    red[tid] = mx;
    __syncthreads();
    for (int s = 128; s > 0; s >>= 1) {
        if (tid < s) red[tid] = fmaxf(red[tid], red[tid + s]);
        __syncthreads();
    }
    mx = red[0];
    __syncthreads();
    float sum = 0.0f;
#pragma unroll
    for (int i = 0; i < 8; i++) { local[i] = expf(local[i] - mx); sum += local[i]; }
    red[tid] = sum;
    __syncthreads();
    for (int s = 128; s > 0; s >>= 1) {
        if (tid < s) red[tid] += red[tid + s];
        __syncthreads();
    }
    const float inv = 1.0f / red[0];
#pragma unroll
    for (int i = 0; i < 8; i++) {
        float w = local[i] * inv;
        g_weights[b * TE + tid + i * 256]   = w;
        out_weights[b * TE + tid + i * 256] = w;
    }
}

__global__ void context_kernel(const float* __restrict__ enc, float* __restrict__ out_context) {
    const int b = blockIdx.x;
    const int e = blockIdx.y * 256 + threadIdx.x;
    __shared__ float sw[TE];
    for (int i = threadIdx.x; i < TE; i += 256) sw[i] = g_weights[b * TE + i];
    __syncthreads();
    const float* base = enc + (size_t)b * TE * Dd + e;
    float acc = 0.0f;
#pragma unroll 8
    for (int t = 0; t < TE; t++) acc = fmaf(sw[t], base[(size_t)t * Dd], acc);
    out_context[b * Dd + e] = acc;
}

// ---------------- launch ----------------
extern "C" void kernel_launch(void* const* d_in, const int* in_sizes, int n_in,
                              void* d_out, int out_size) {
    const float* enc = (const float*)d_in[0];
    const float* dec = (const float*)d_in[1];
    const float* W_a = (const float*)d_in[2];
    const float* U_a = (const float*)d_in[3];
    const float* V_a = (const float*)d_in[4];
    float* out = (float*)d_out;
    float* out_context = out;            // 32*1024
    float* out_weights = out + Bz * Dd;  // 32*2048

    static int smem_set = 0;
    if (!smem_set) {
        cudaFuncSetAttribute(gemm_score_mma, cudaFuncAttributeMaxDynamicSharedMemorySize, SMEM_TOTAL);
        smem_set = 1;
    }

    convert_A_kernel<<<(Mrows * (Dd / 8)) / 256, 256>>>(enc);
    convert_W_kernel<<<(Dd * Dd) / 256, 256>>>(W_a);
    zero_kernel<<<(Bz * TE + 255) / 256, 256>>>();
    {
        dim3 g(Dd / 256, 32);
        dU_kernel<<<g, 256>>>(dec, U_a);
    }
    gemm_score_mma<<<(Mrows / BM) * (Dd / BN), 256, SMEM_TOTAL>>>(V_a);
    softmax_kernel<<<Bz, 256>>>(out_weights);
    {
        dim3 g(Bz, Dd / 256);
        context_kernel<<<g, 256>>>(enc, out_context);
    }
}

// round 9
// speedup vs baseline: 5.4366x; 1.5502x over previous
#include <cuda_runtime.h>
#include <cuda_fp16.h>
#include <math.h>
#include <stdint.h>

// ---------------- problem constants ----------------
#define Bz 32
#define TE 2048
#define TDd 64
#define Dd 1024
#define Mrows (Bz * TE)      // 65536

// ---------------- scratch (device globals) ----------------
__device__ __half g_A1[(size_t)Mrows * Dd];   // fp16(enc)
__device__ __half g_B1[(size_t)Dd * Dd];      // W^T fp16 : [n][k]
__device__ float g_dU[Bz * Dd];
__device__ float g_scores[Bz * TE];
__device__ float g_weights[Bz * TE];

// ---------------- helpers ----------------
__device__ __forceinline__ uint32_t smem_to_u32(const void* p) {
    uint32_t a;
    asm("{ .reg .u64 t; cvta.to.shared.u64 t, %1; cvt.u32.u64 %0, t; }" : "=r"(a) : "l"(p));
    return a;
}
__device__ __forceinline__ void cp16(uint32_t s, const void* g) {
    asm volatile("cp.async.cg.shared.global [%0], [%1], 16;" :: "r"(s), "l"(g));
}
#define CP_COMMIT() asm volatile("cp.async.commit_group;" ::: "memory")
#define CP_WAIT(n)  asm volatile("cp.async.wait_group %0;" :: "n"(n) : "memory")
#define LDSM_X4(r0, r1, r2, r3, addr) \
    asm volatile("ldmatrix.sync.aligned.m8n8.x4.shared.b16 {%0,%1,%2,%3}, [%4];" \
        : "=r"(r0), "=r"(r1), "=r"(r2), "=r"(r3) : "r"(addr))
#define MMA16816F(d0, d1, d2, d3, a0, a1, a2, a3, b0, b1) \
    asm volatile("mma.sync.aligned.m16n8k16.row.col.f32.f16.f16.f32 " \
        "{%0,%1,%2,%3}, {%4,%5,%6,%7}, {%8,%9}, {%0,%1,%2,%3};" \
        : "+f"(d0), "+f"(d1), "+f"(d2), "+f"(d3) \
        : "r"(a0), "r"(a1), "r"(a2), "r"(a3), "r"(b0), "r"(b1))

__device__ __forceinline__ uint32_t sw128(uint32_t off) {
    return off ^ ((off >> 3) & 0x70);
}

// ---------------- GEMM tiling ----------------
#define BM 128
#define BN 128
#define BKE 64                      // fp16 k per chunk (128 B rows)
#define NKC1 16                     // single phase * 16 k-chunks
#define STG_B 32768                 // per-stage bytes: A 16K + B 16K
#define SMEM_TOTAL (3 * STG_B)      // 96 KB

// ---------------- setup kernels ----------------
// 8 floats per thread
__global__ void convert_A_kernel(const float* __restrict__ enc) {
    size_t i = ((size_t)blockIdx.x * blockDim.x + threadIdx.x) * 8;
    float4 v0 = *(const float4*)(enc + i);
    float4 v1 = *(const float4*)(enc + i + 4);
    __half2 h[4];
    h[0] = __floats2half2_rn(v0.x, v0.y);
    h[1] = __floats2half2_rn(v0.z, v0.w);
    h[2] = __floats2half2_rn(v1.x, v1.y);
    h[3] = __floats2half2_rn(v1.z, v1.w);
    *(uint4*)(g_A1 + i) = *(uint4*)h;
}

__global__ void convert_W_kernel(const float* __restrict__ W) {
    int id = blockIdx.x * 256 + threadIdx.x;
    int n = id >> 10, k = id & 1023;
    g_B1[(size_t)n * Dd + k] = __float2half(W[(size_t)k * Dd + n]);  // transpose
}

__global__ void zero_kernel() {
    int i = blockIdx.x * blockDim.x + threadIdx.x;
    if (i < Bz * TE) g_scores[i] = 0.0f;
    if (i < Bz * Dd) g_dU[i] = 0.0f;
}

// dU[b][f] = sum_k dec_last[b][k] * U[k][f]  ; grid (4, 32)
__global__ void dU_kernel(const float* __restrict__ dec, const float* __restrict__ U) {
    const int f  = blockIdx.x * 256 + threadIdx.x;
    const int k0 = blockIdx.y * 32;
    __shared__ float sdec[Bz][32];
#pragma unroll
    for (int j = 0; j < 4; j++) {
        int idx = threadIdx.x + j * 256;
        int b = idx >> 5, kk = idx & 31;
        sdec[b][kk] = dec[((size_t)b * TDd + (TDd - 1)) * Dd + k0 + kk];
    }
    __syncthreads();
    float acc[Bz];
#pragma unroll
    for (int b = 0; b < Bz; b++) acc[b] = 0.0f;
#pragma unroll
    for (int kk = 0; kk < 32; kk++) {
        float u = U[(size_t)(k0 + kk) * Dd + f];
#pragma unroll
        for (int b = 0; b < Bz; b++) acc[b] = fmaf(u, sdec[b][kk], acc[b]);
    }
#pragma unroll
    for (int b = 0; b < Bz; b++) atomicAdd(&g_dU[b * Dd + f], acc[b]);
}

// ---------------- fused GEMM + epilogue ----------------
__device__ __forceinline__ void load_chunk(uint32_t sbase, int stage, int c,
                                           int mbase, int nbase, int tid) {
    const int kb = c * BKE;
    uint32_t sA = sbase + stage * STG_B;
    uint32_t sB = sA + 16384;
#pragma unroll
    for (int i = 0; i < 4; i++) {
        int u = tid + i * 256;                 // 0..1023
        int r = u >> 3, ch = u & 7;
        uint32_t off = sw128((uint32_t)(r * 128 + ch * 16));
        cp16(sA + off, g_A1 + (size_t)(mbase + r) * Dd + kb + ch * 8);
        cp16(sB + off, g_B1 + (size_t)(nbase + r) * Dd + kb + ch * 8);
    }
    CP_COMMIT();
}

__global__ void __launch_bounds__(256, 2) gemm_score_mma(const float* __restrict__ V) {
    extern __shared__ char smem[];
    uint32_t sbase = smem_to_u32(smem);

    const int tid  = threadIdx.x;
    const int wid  = tid >> 5;
    const int lane = tid & 31;
    const int wm   = wid >> 2;      // 0..1
    const int wn   = wid & 3;       // 0..3

    const int nblk  = blockIdx.x & 7;
    const int mblk  = blockIdx.x >> 3;
    const int mbase = mblk * BM;
    const int nbase = nblk * BN;
    const int b     = mbase >> 11;

    float acc[4][4][4];
#pragma unroll
    for (int mt = 0; mt < 4; mt++)
#pragma unroll
        for (int nt = 0; nt < 4; nt++)
#pragma unroll
            for (int i = 0; i < 4; i++) acc[mt][nt][i] = 0.0f;

    const int a_r  = lane & 15;
    const int a_kc = lane >> 4;
    const int b_n  = ((lane >> 4) & 1) * 8 + (lane & 7);
    const int b_kc = (lane >> 3) & 1;

    // prologue: stages 0,1
    load_chunk(sbase, 0, 0, mbase, nbase, tid);
    load_chunk(sbase, 1, 1, mbase, nbase, tid);

    int stage = 0;
    for (int c = 0; c < NKC1; c++) {
        if (c + 2 < NKC1) { CP_WAIT(1); } else { CP_WAIT(0); }
        __syncthreads();
        if (c + 2 < NKC1) {
            int ns = stage + 2; if (ns >= 3) ns -= 3;
            load_chunk(sbase, ns, c + 2, mbase, nbase, tid);
        }

        const uint32_t sA = sbase + stage * STG_B;
        const uint32_t sB = sA + 16384;
#pragma unroll
        for (int ks = 0; ks < 4; ks++) {
            uint32_t af[4][4], bf[2][4];
#pragma unroll
            for (int mt = 0; mt < 4; mt++) {
                int row = wm * 64 + mt * 16 + a_r;
                uint32_t off = sw128((uint32_t)(row * 128 + (ks * 2 + a_kc) * 16));
                LDSM_X4(af[mt][0], af[mt][1], af[mt][2], af[mt][3], sA + off);
            }
#pragma unroll
            for (int p = 0; p < 2; p++) {
                int row = wn * 32 + p * 16 + b_n;
                uint32_t off = sw128((uint32_t)(row * 128 + (ks * 2 + b_kc) * 16));
                LDSM_X4(bf[p][0], bf[p][1], bf[p][2], bf[p][3], sB + off);
            }
#pragma unroll
            for (int mt = 0; mt < 4; mt++)
#pragma unroll
                for (int nt = 0; nt < 4; nt++)
                    MMA16816F(acc[mt][nt][0], acc[mt][nt][1], acc[mt][nt][2], acc[mt][nt][3],
                              af[mt][0], af[mt][1], af[mt][2], af[mt][3],
                              bf[nt >> 1][(nt & 1) * 2], bf[nt >> 1][(nt & 1) * 2 + 1]);
        }
        stage++; if (stage >= 3) stage = 0;
    }

    // ---- fused epilogue: scores[m] += sum_n V[n]*tanh(C[m][n] + dU[b][n]) ----
    const int q = lane >> 2;
    const int t4 = lane & 3;
#pragma unroll
    for (int mt = 0; mt < 4; mt++) {
        float s0 = 0.0f, s1 = 0.0f;
#pragma unroll
        for (int nt = 0; nt < 4; nt++) {
            int n0 = nbase + wn * 32 + nt * 8 + 2 * t4;
            float v0 = V[n0], v1 = V[n0 + 1];
            float u0 = g_dU[b * Dd + n0], u1 = g_dU[b * Dd + n0 + 1];
            s0 = fmaf(v0, tanhf(acc[mt][nt][0] + u0), s0);
            s0 = fmaf(v1, tanhf(acc[mt][nt][1] + u1), s0);
            s1 = fmaf(v0, tanhf(acc[mt][nt][2] + u0), s1);
            s1 = fmaf(v1, tanhf(acc[mt][nt][3] + u1), s1);
        }
        s0 += __shfl_xor_sync(0xFFFFFFFF, s0, 1);
        s0 += __shfl_xor_sync(0xFFFFFFFF, s0, 2);
        s1 += __shfl_xor_sync(0xFFFFFFFF, s1, 1);
        s1 += __shfl_xor_sync(0xFFFFFFFF, s1, 2);
        if (t4 == 0) {
            int row = mbase + wm * 64 + mt * 16 + q;
            atomicAdd(&g_scores[row], s0);
            atomicAdd(&g_scores[row + 8], s1);
        }
    }
}

// ---------------- softmax & context ----------------
__global__ void softmax_kernel(float* __restrict__ out_weights) {
    const int b = blockIdx.x;
    const int tid = threadIdx.x;
    __shared__ float red[256];
    float local[8];
    float mx = -INFINITY;
#pragma unroll
    for (int i = 0; i < 8; i++) {
        local[i] = g_scores[b * TE + tid + i * 256];
        mx = fmaxf(mx, local[i]);
    }
    red[tid] = mx;
    __syncthreads();
    for (int s = 128; s > 0; s >>= 1) {
        if (tid < s) red[tid] = fmaxf(red[tid], red[tid + s]);
        __syncthreads();
    }
    mx = red[0];
    __syncthreads();
    float sum = 0.0f;
#pragma unroll
    for (int i = 0; i < 8; i++) { local[i] = expf(local[i] - mx); sum += local[i]; }
    red[tid] = sum;
    __syncthreads();
    for (int s = 128; s > 0; s >>= 1) {
        if (tid < s) red[tid] += red[tid + s];
        __syncthreads();
    }
    const float inv = 1.0f / red[0];
#pragma unroll
    for (int i = 0; i < 8; i++) {
        float w = local[i] * inv;
        g_weights[b * TE + tid + i * 256]   = w;
        out_weights[b * TE + tid + i * 256] = w;
    }
}

__global__ void context_kernel(const float* __restrict__ enc, float* __restrict__ out_context) {
    const int b = blockIdx.x;
    const int e = blockIdx.y * 256 + threadIdx.x;
    __shared__ float sw[TE];
    for (int i = threadIdx.x; i < TE; i += 256) sw[i] = g_weights[b * TE + i];
    __syncthreads();
    const float* base = enc + (size_t)b * TE * Dd + e;
    float acc = 0.0f;
#pragma unroll 8
    for (int t = 0; t < TE; t++) acc = fmaf(sw[t], base[(size_t)t * Dd], acc);
    out_context[b * Dd + e] = acc;
}

// ---------------- launch ----------------
extern "C" void kernel_launch(void* const* d_in, const int* in_sizes, int n_in,
                              void* d_out, int out_size) {
    const float* enc = (const float*)d_in[0];
    const float* dec = (const float*)d_in[1];
    const float* W_a = (const float*)d_in[2];
    const float* U_a = (const float*)d_in[3];
    const float* V_a = (const float*)d_in[4];
    float* out = (float*)d_out;
    float* out_context = out;            // 32*1024
    float* out_weights = out + Bz * Dd;  // 32*2048

    static int smem_set = 0;
    if (!smem_set) {
        cudaFuncSetAttribute(gemm_score_mma, cudaFuncAttributeMaxDynamicSharedMemorySize, SMEM_TOTAL);
        smem_set = 1;
    }

    convert_A_kernel<<<(Mrows * (Dd / 8)) / 256, 256>>>(enc);
    convert_W_kernel<<<(Dd * Dd) / 256, 256>>>(W_a);
    zero_kernel<<<(Bz * TE + 255) / 256, 256>>>();
    {
        dim3 g(Dd / 256, 32);
        dU_kernel<<<g, 256>>>(dec, U_a);
    }
    gemm_score_mma<<<(Mrows / BM) * (Dd / BN), 256, SMEM_TOTAL>>>(V_a);
    softmax_kernel<<<Bz, 256>>>(out_weights);
    {
        dim3 g(Bz, Dd / 256);
        context_kernel<<<g, 256>>>(enc, out_context);
    }
}

// round 10
// speedup vs baseline: 5.5138x; 1.0142x over previous
#include <cuda_runtime.h>
#include <cuda_fp16.h>
#include <math.h>
#include <stdint.h>

// ---------------- problem constants ----------------
#define Bz 32
#define TE 2048
#define TDd 64
#define Dd 1024
#define Mrows (Bz * TE)      // 65536

// ---------------- scratch (device globals) ----------------
__device__ __half g_A1[(size_t)Mrows * Dd];   // fp16(enc)
__device__ __half g_B1[(size_t)Dd * Dd];      // W^T fp16 : [n][k]
__device__ float g_dU[Bz * Dd];
__device__ float g_scores[Bz * TE];
__device__ float g_weights[Bz * TE];

// ---------------- helpers ----------------
__device__ __forceinline__ uint32_t smem_to_u32(const void* p) {
    uint32_t a;
    asm("{ .reg .u64 t; cvta.to.shared.u64 t, %1; cvt.u32.u64 %0, t; }" : "=r"(a) : "l"(p));
    return a;
}
__device__ __forceinline__ void cp16(uint32_t s, const void* g) {
    asm volatile("cp.async.cg.shared.global [%0], [%1], 16;" :: "r"(s), "l"(g));
}
#define CP_COMMIT() asm volatile("cp.async.commit_group;" ::: "memory")
#define CP_WAIT(n)  asm volatile("cp.async.wait_group %0;" :: "n"(n) : "memory")
#define LDSM_X4(r0, r1, r2, r3, addr) \
    asm volatile("ldmatrix.sync.aligned.m8n8.x4.shared.b16 {%0,%1,%2,%3}, [%4];" \
        : "=r"(r0), "=r"(r1), "=r"(r2), "=r"(r3) : "r"(addr))
#define MMA16816F(d0, d1, d2, d3, a0, a1, a2, a3, b0, b1) \
    asm volatile("mma.sync.aligned.m16n8k16.row.col.f32.f16.f16.f32 " \
        "{%0,%1,%2,%3}, {%4,%5,%6,%7}, {%8,%9}, {%0,%1,%2,%3};" \
        : "+f"(d0), "+f"(d1), "+f"(d2), "+f"(d3) \
        : "r"(a0), "r"(a1), "r"(a2), "r"(a3), "r"(b0), "r"(b1))

__device__ __forceinline__ uint32_t sw128(uint32_t off) {
    return off ^ ((off >> 3) & 0x70);
}
// fast tanh: 2 MUFU ops, abs err ~1e-7
__device__ __forceinline__ float fast_tanh(float x) {
    float ax = fabsf(x);
    float e  = __expf(2.0f * ax);
    float t  = 1.0f - __fdividef(2.0f, e + 1.0f);
    return copysignf(t, x);
}

// ---------------- GEMM tiling ----------------
#define BM 128
#define BN 128
#define BKE 64                      // fp16 k per chunk (128 B rows)
#define NKC1 16                     // 16 k-chunks
#define STG_B 32768                 // per-stage bytes: A 16K + B 16K
#define SMEM_TOTAL (3 * STG_B)      // 96 KB

// ---------------- setup kernels ----------------
__global__ void convert_A_kernel(const float* __restrict__ enc) {
    size_t i = ((size_t)blockIdx.x * blockDim.x + threadIdx.x) * 8;
    float4 v0 = *(const float4*)(enc + i);
    float4 v1 = *(const float4*)(enc + i + 4);
    __half2 h[4];
    h[0] = __floats2half2_rn(v0.x, v0.y);
    h[1] = __floats2half2_rn(v0.z, v0.w);
    h[2] = __floats2half2_rn(v1.x, v1.y);
    h[3] = __floats2half2_rn(v1.z, v1.w);
    *(uint4*)(g_A1 + i) = *(uint4*)h;
}

// W transpose-convert + zero scores/dU (folded)
__global__ void convert_W_kernel(const float* __restrict__ W) {
    int id = blockIdx.x * 256 + threadIdx.x;
    int n = id >> 10, k = id & 1023;
    g_B1[(size_t)n * Dd + k] = __float2half(W[(size_t)k * Dd + n]);
    if (id < Bz * TE) g_scores[id] = 0.0f;
    if (id < Bz * Dd) g_dU[id] = 0.0f;
}

// dU[b][f] = sum_k dec_last[b][k] * U[k][f]  ; grid (4, 32)
__global__ void dU_kernel(const float* __restrict__ dec, const float* __restrict__ U) {
    const int f  = blockIdx.x * 256 + threadIdx.x;
    const int k0 = blockIdx.y * 32;
    __shared__ float sdec[Bz][32];
#pragma unroll
    for (int j = 0; j < 4; j++) {
        int idx = threadIdx.x + j * 256;
        int b = idx >> 5, kk = idx & 31;
        sdec[b][kk] = dec[((size_t)b * TDd + (TDd - 1)) * Dd + k0 + kk];
    }
    __syncthreads();
    float acc[Bz];
#pragma unroll
    for (int b = 0; b < Bz; b++) acc[b] = 0.0f;
#pragma unroll
    for (int kk = 0; kk < 32; kk++) {
        float u = U[(size_t)(k0 + kk) * Dd + f];
#pragma unroll
        for (int b = 0; b < Bz; b++) acc[b] = fmaf(u, sdec[b][kk], acc[b]);
    }
#pragma unroll
    for (int b = 0; b < Bz; b++) atomicAdd(&g_dU[b * Dd + f], acc[b]);
}

// ---------------- fused GEMM + epilogue ----------------
__device__ __forceinline__ void load_chunk(uint32_t sbase, int stage, int c,
                                           int mbase, int nbase, int tid) {
    const int kb = c * BKE;
    uint32_t sA = sbase + stage * STG_B;
    uint32_t sB = sA + 16384;
#pragma unroll
    for (int i = 0; i < 4; i++) {
        int u = tid + i * 256;                 // 0..1023
        int r = u >> 3, ch = u & 7;
        uint32_t off = sw128((uint32_t)(r * 128 + ch * 16));
        cp16(sA + off, g_A1 + (size_t)(mbase + r) * Dd + kb + ch * 8);
        cp16(sB + off, g_B1 + (size_t)(nbase + r) * Dd + kb + ch * 8);
    }
    CP_COMMIT();
}

__global__ void __launch_bounds__(256, 2) gemm_score_mma(const float* __restrict__ V) {
    extern __shared__ char smem[];
    uint32_t sbase = smem_to_u32(smem);

    const int tid  = threadIdx.x;
    const int wid  = tid >> 5;
    const int lane = tid & 31;
    const int wm   = wid >> 2;      // 0..1
    const int wn   = wid & 3;       // 0..3

    const int nblk  = blockIdx.x & 7;
    const int mblk  = blockIdx.x >> 3;
    const int mbase = mblk * BM;
    const int nbase = nblk * BN;
    const int b     = mbase >> 11;

    float acc[4][4][4];
#pragma unroll
    for (int mt = 0; mt < 4; mt++)
#pragma unroll
        for (int nt = 0; nt < 4; nt++)
#pragma unroll
            for (int i = 0; i < 4; i++) acc[mt][nt][i] = 0.0f;

    const int a_r  = lane & 15;
    const int a_kc = lane >> 4;
    const int b_n  = ((lane >> 4) & 1) * 8 + (lane & 7);
    const int b_kc = (lane >> 3) & 1;

    load_chunk(sbase, 0, 0, mbase, nbase, tid);
    load_chunk(sbase, 1, 1, mbase, nbase, tid);

    int stage = 0;
    for (int c = 0; c < NKC1; c++) {
        if (c + 2 < NKC1) { CP_WAIT(1); } else { CP_WAIT(0); }
        __syncthreads();
        if (c + 2 < NKC1) {
            int ns = stage + 2; if (ns >= 3) ns -= 3;
            load_chunk(sbase, ns, c + 2, mbase, nbase, tid);
        }

        const uint32_t sA = sbase + stage * STG_B;
        const uint32_t sB = sA + 16384;
#pragma unroll
        for (int ks = 0; ks < 4; ks++) {
            uint32_t af[4][4], bf[2][4];
#pragma unroll
            for (int mt = 0; mt < 4; mt++) {
                int row = wm * 64 + mt * 16 + a_r;
                uint32_t off = sw128((uint32_t)(row * 128 + (ks * 2 + a_kc) * 16));
                LDSM_X4(af[mt][0], af[mt][1], af[mt][2], af[mt][3], sA + off);
            }
#pragma unroll
            for (int p = 0; p < 2; p++) {
                int row = wn * 32 + p * 16 + b_n;
                uint32_t off = sw128((uint32_t)(row * 128 + (ks * 2 + b_kc) * 16));
                LDSM_X4(bf[p][0], bf[p][1], bf[p][2], bf[p][3], sB + off);
            }
#pragma unroll
            for (int mt = 0; mt < 4; mt++)
#pragma unroll
                for (int nt = 0; nt < 4; nt++)
                    MMA16816F(acc[mt][nt][0], acc[mt][nt][1], acc[mt][nt][2], acc[mt][nt][3],
                              af[mt][0], af[mt][1], af[mt][2], af[mt][3],
                              bf[nt >> 1][(nt & 1) * 2], bf[nt >> 1][(nt & 1) * 2 + 1]);
        }
        stage++; if (stage >= 3) stage = 0;
    }

    // ---- fused epilogue: scores[m] += sum_n V[n]*tanh(C[m][n] + dU[b][n]) ----
    const int q = lane >> 2;
    const int t4 = lane & 3;
#pragma unroll
    for (int mt = 0; mt < 4; mt++) {
        float s0 = 0.0f, s1 = 0.0f;
#pragma unroll
        for (int nt = 0; nt < 4; nt++) {
            int n0 = nbase + wn * 32 + nt * 8 + 2 * t4;
            float v0 = V[n0], v1 = V[n0 + 1];
            float u0 = g_dU[b * Dd + n0], u1 = g_dU[b * Dd + n0 + 1];
            s0 = fmaf(v0, fast_tanh(acc[mt][nt][0] + u0), s0);
            s0 = fmaf(v1, fast_tanh(acc[mt][nt][1] + u1), s0);
            s1 = fmaf(v0, fast_tanh(acc[mt][nt][2] + u0), s1);
            s1 = fmaf(v1, fast_tanh(acc[mt][nt][3] + u1), s1);
        }
        s0 += __shfl_xor_sync(0xFFFFFFFF, s0, 1);
        s0 += __shfl_xor_sync(0xFFFFFFFF, s0, 2);
        s1 += __shfl_xor_sync(0xFFFFFFFF, s1, 1);
        s1 += __shfl_xor_sync(0xFFFFFFFF, s1, 2);
        if (t4 == 0) {
            int row = mbase + wm * 64 + mt * 16 + q;
            atomicAdd(&g_scores[row], s0);
            atomicAdd(&g_scores[row + 8], s1);
        }
    }
}

// ---------------- softmax & context ----------------
__global__ void softmax_kernel(float* __restrict__ out_weights) {
    const int b = blockIdx.x;
    const int tid = threadIdx.x;
    __shared__ float red[256];
    float local[8];
    float mx = -INFINITY;
#pragma unroll
    for (int i = 0; i < 8; i++) {
        local[i] = g_scores[b * TE + tid + i * 256];
        mx = fmaxf(mx, local[i]);
    }
    red[tid] = mx;
    __syncthreads();
    for (int s = 128; s > 0; s >>= 1) {
        if (tid < s) red[tid] = fmaxf(red[tid], red[tid + s]);
        __syncthreads();
    }
    mx = red[0];
    __syncthreads();
    float sum = 0.0f;
#pragma unroll
    for (int i = 0; i < 8; i++) { local[i] = __expf(local[i] - mx); sum += local[i]; }
    red[tid] = sum;
    __syncthreads();
    for (int s = 128; s > 0; s >>= 1) {
        if (tid < s) red[tid] += red[tid + s];
        __syncthreads();
    }
    const float inv = 1.0f / red[0];
#pragma unroll
    for (int i = 0; i < 8; i++) {
        float w = local[i] * inv;
        g_weights[b * TE + tid + i * 256]   = w;
        out_weights[b * TE + tid + i * 256] = w;
    }
}

// context from fp16 A1 (same [b*TE+t][e] layout as enc)
__global__ void context_kernel(float* __restrict__ out_context) {
    const int b = blockIdx.x;
    const int e = blockIdx.y * 256 + threadIdx.x;
    __shared__ float sw[TE];
    for (int i = threadIdx.x; i < TE; i += 256) sw[i] = g_weights[b * TE + i];
    __syncthreads();
    const __half* base = g_A1 + (size_t)b * TE * Dd + e;
    float acc = 0.0f;
#pragma unroll 8
    for (int t = 0; t < TE; t++)
        acc = fmaf(sw[t], __half2float(base[(size_t)t * Dd]), acc);
    out_context[b * Dd + e] = acc;
}

// ---------------- launch ----------------
extern "C" void kernel_launch(void* const* d_in, const int* in_sizes, int n_in,
                              void* d_out, int out_size) {
    const float* enc = (const float*)d_in[0];
    const float* dec = (const float*)d_in[1];
    const float* W_a = (const float*)d_in[2];
    const float* U_a = (const float*)d_in[3];
    const float* V_a = (const float*)d_in[4];
    float* out = (float*)d_out;
    float* out_context = out;            // 32*1024
    float* out_weights = out + Bz * Dd;  // 32*2048

    static int smem_set = 0;
    if (!smem_set) {
        cudaFuncSetAttribute(gemm_score_mma, cudaFuncAttributeMaxDynamicSharedMemorySize, SMEM_TOTAL);
        smem_set = 1;
    }

    convert_A_kernel<<<(Mrows * (Dd / 8)) / 256, 256>>>(enc);
    convert_W_kernel<<<(Dd * Dd) / 256, 256>>>(W_a);
    {
        dim3 g(Dd / 256, 32);
        dU_kernel<<<g, 256>>>(dec, U_a);
    }
    gemm_score_mma<<<(Mrows / BM) * (Dd / BN), 256, SMEM_TOTAL>>>(V_a);
    softmax_kernel<<<Bz, 256>>>(out_weights);
    {
        dim3 g(Bz, Dd / 256);
        context_kernel<<<g, 256>>>(out_context);
    }
}